// round 9
// baseline (speedup 1.0000x reference)
#include <cuda_runtime.h>
#include <cuda_bf16.h>
#include <math.h>
#include <stdint.h>

#define TSTEPS 12
#define BATCH  8

// ---------------- scratch (static device globals) ---------------------------
__device__ float  g_seq1[(size_t)TSTEPS * BATCH * 64 * 64 * 64];
__device__ float  g_seq2[(size_t)TSTEPS * BATCH * 128 * 32 * 32];
__device__ float  g_h3a [(size_t)BATCH * 128 * 16 * 16];
__device__ float  g_h3b [(size_t)BATCH * 128 * 16 * 16];
// bf16-split activations: uint4 per CHANNEL-PAIR per pixel:
//  .x = dup(hi(ch c)), .y = dup(hi(ch c+4)), .z = dup(lo(ch c)), .w = dup(lo(ch c+4))
//  plane index for channel c: (c>>3)*4 + (c&3); slot = (c>>2)&1
__device__ uint4  g_xsp1[(size_t)TSTEPS * BATCH * 32 * 64 * 64];
__device__ uint4  g_xsp2[(size_t)TSTEPS * BATCH * 64 * 32 * 32];
__device__ uint4  g_xsp3[(size_t)TSTEPS * BATCH * 64 * 16 * 16];
__device__ uint4  g_hsp1a[(size_t)BATCH * 32 * 64 * 64];
__device__ uint4  g_hsp1b[(size_t)BATCH * 32 * 64 * 64];
__device__ uint4  g_hsp2a[(size_t)BATCH * 64 * 32 * 32];
__device__ uint4  g_hsp2b[(size_t)BATCH * 64 * 32 * 32];
__device__ uint4  g_hsp3a[(size_t)BATCH * 64 * 16 * 16];
__device__ uint4  g_hsp3b[(size_t)BATCH * 64 * 16 * 16];
__device__ uint4  g_rhsp[(size_t)BATCH * 32 * 64 * 64];
__device__ uint4  g_zsp [(size_t)BATCH * 32 * 64 * 64];
__device__ float  g_zr  [(size_t)BATCH * 128 * 64 * 64];
__device__ float  g_part[(size_t)8388608];
__device__ float  g_zero[(size_t)BATCH * 64 * 64 * 64];
// packed bf16x2 weights (low16 = wHi, high16 = wLo), fp32 weight indexing
__device__ uint32_t g_wcvt[(size_t)5529600];

// ---------------- bf16 split helpers ----------------------------------------
__device__ __forceinline__ void bsplit(float v, uint16_t& hb, uint16_t& lb) {
    __nv_bfloat16 h = __float2bfloat16(v);
    float hf = __bfloat162float(h);
    __nv_bfloat16 l = __float2bfloat16(v - hf);
    hb = __bfloat16_as_ushort(h);
    lb = __bfloat16_as_ushort(l);
}
__device__ __forceinline__ uint32_t dup16(uint16_t b) {
    return ((uint32_t)b << 16) | (uint32_t)b;
}
__device__ __forceinline__ void storeSplit(uint4* planeBase, int c, long long HW,
                                           long long pix, float v) {
    uint16_t hb, lb;
    bsplit(v, hb, lb);
    uint32_t* p = (uint32_t*)(planeBase + (long long)((c >> 3) * 4 + (c & 3)) * HW + pix);
    int slot = (c >> 2) & 1;
    p[slot] = dup16(hb);
    p[2 + slot] = dup16(lb);
}
__device__ __forceinline__ float loadSplit(const uint4* planeBase, int c, long long HW,
                                           long long pix) {
    const uint32_t* p = (const uint32_t*)(planeBase + (long long)((c >> 3) * 4 + (c & 3)) * HW + pix);
    int slot = (c >> 2) & 1;
    return __bfloat162float(__ushort_as_bfloat16((uint16_t)p[slot])) +
           __bfloat162float(__ushort_as_bfloat16((uint16_t)p[2 + slot]));
}

__global__ void zerok(float* p, uint4* p2, int n, int n2) {
    int i = blockIdx.x * blockDim.x + threadIdx.x;
    if (i < n) p[i] = 0.0f;
    if (i < n2) p2[i] = make_uint4(0, 0, 0, 0);
}
__global__ void copyk(float* __restrict__ dst, const float* __restrict__ src, int n) {
    int i = blockIdx.x * blockDim.x + threadIdx.x;
    if (i < n) dst[i] = src[i];
}
__global__ void wcvtK(const float* __restrict__ w, uint32_t* __restrict__ o, int n) {
    int i = blockIdx.x * blockDim.x + threadIdx.x;
    if (i >= n) return;
    uint16_t hb, lb;
    bsplit(w[i], hb, lb);
    o[i] = ((uint32_t)lb << 16) | (uint32_t)hb;
}

// ---------------- cp.async helpers ------------------------------------------
__device__ __forceinline__ void cp4(uint32_t saddr, const void* g, bool ok) {
    int sz = ok ? 4 : 0;
    asm volatile("cp.async.ca.shared.global [%0], [%1], 4, %2;\n"
                 :: "r"(saddr), "l"(g), "r"(sz));
}
__device__ __forceinline__ void cp16(uint32_t saddr, const void* g, bool ok) {
    int sz = ok ? 16 : 0;
    asm volatile("cp.async.cg.shared.global [%0], [%1], 16, %2;\n"
                 :: "r"(saddr), "l"(g), "r"(sz));
}
__device__ __forceinline__ void cpCommit() {
    asm volatile("cp.async.commit_group;\n" ::: "memory");
}
template <int N>
__device__ __forceinline__ void cpWait() {
    asm volatile("cp.async.wait_group %0;\n" :: "n"(N) : "memory");
}
__device__ __forceinline__ void mma16(float* d, uint32_t a0, uint32_t a1, uint32_t a2,
                                      uint32_t a3, uint32_t b0, uint32_t b1) {
    asm volatile(
        "mma.sync.aligned.m16n8k16.row.col.f32.bf16.bf16.f32 "
        "{%0,%1,%2,%3}, {%4,%5,%6,%7}, {%8,%9}, {%0,%1,%2,%3};"
        : "+f"(d[0]), "+f"(d[1]), "+f"(d[2]), "+f"(d[3])
        : "r"(a0), "r"(a1), "r"(a2), "r"(a3), "r"(b0), "r"(b1));
}

// ---------------------------------------------------------------------------
// Strided conv k4 s2 p1, batched over T. Output written bf16-SPLIT (uint4 planes).
// ---------------------------------------------------------------------------
template <int TX, int TY, int OC>
__global__ void conv4s2(const float* __restrict__ in,
                        long long strideB, long long strideT,
                        const float* __restrict__ w, const float* __restrict__ bias,
                        uint4* __restrict__ out,
                        int Cin, int Cout, int Hin, int Win)
{
    const int Hout = Hin >> 1, Wout = Win >> 1;
    const int ocG = Cout / OC;
    int z = blockIdx.z;
    const int ocb = z % ocG; z /= ocG;
    const int b   = z % BATCH;
    const int t   = z / BATCH;
    const int y0  = blockIdx.y * TY;
    const int x0  = blockIdx.x * TX;

    constexpr int IW = 2 * TX + 2;
    constexpr int IH = 2 * TY + 2;
    __shared__ float s_in[IH * IW];
    __shared__ float s_w[OC * 16];

    const int tid = threadIdx.y * TX + threadIdx.x;
    const int nth = TX * TY;
    const float* base = in + (long long)b * strideB + (long long)t * strideT;

    float acc[OC];
#pragma unroll
    for (int oc = 0; oc < OC; oc++) acc[oc] = 0.0f;

    for (int ic = 0; ic < Cin; ic++) {
        const float* src = base + (long long)ic * Hin * Win;
        for (int idx = tid; idx < IH * IW; idx += nth) {
            int iy = 2 * y0 - 1 + idx / IW;
            int ix = 2 * x0 - 1 + idx % IW;
            s_in[idx] = (iy >= 0 && iy < Hin && ix >= 0 && ix < Win)
                            ? src[(long long)iy * Win + ix] : 0.0f;
        }
        for (int idx = tid; idx < OC * 16; idx += nth) {
            int oc = idx / 16, k = idx % 16;
            s_w[idx] = w[(((long long)(ocb * OC + oc)) * Cin + ic) * 16 + k];
        }
        __syncthreads();
#pragma unroll
        for (int kh = 0; kh < 4; kh++)
#pragma unroll
            for (int kw = 0; kw < 4; kw++) {
                float inv = s_in[(2 * threadIdx.y + kh) * IW + 2 * threadIdx.x + kw];
#pragma unroll
                for (int oc = 0; oc < OC; oc++)
                    acc[oc] = fmaf(inv, s_w[oc * 16 + kh * 4 + kw], acc[oc]);
            }
        __syncthreads();
    }

    const int y = y0 + threadIdx.y, x = x0 + threadIdx.x;
    const long long HWo = (long long)Hout * Wout;
    uint4* ob = out + (long long)(t * BATCH + b) * (Cout >> 1) * HWo;
#pragma unroll
    for (int oc = 0; oc < 4; oc++) {
        int c0 = ocb * OC + oc;
        uint16_t h0, l0, h1, l1;
        bsplit(acc[oc] + bias[c0], h0, l0);
        bsplit(acc[oc + 4] + bias[c0 + 4], h1, l1);
        ob[(long long)(ocb * 4 + oc) * HWo + (long long)y * Wout + x]
            = make_uint4(dup16(h0), dup16(h1), dup16(l0), dup16(l1));
    }
}

// ---------------------------------------------------------------------------
// 5x5 conv s1 p2, implicit GEMM, split-BF16 mma.sync.m16n8k16.
// Block 128 thr (4 warps). Tile: TX x 8 px rows, 32 OUTPUT CHANNELS (2 oc-tiles
// per warp reusing each B fragment). B fragment = ONE LDS.128 of the producer's
// native uint4 (hh0,hh1,ll0,ll1): hi-MMA uses (.x,.y), lo-MMA uses (.z,.w).
// smem: input [2buf][4 pair-planes][SPAD] uint4; weights [2buf][25][2tl][16oc][4t][2half].
// EPI 0: fused sigmoid -> zr fp32 + rh split (KS must be 1). EPI 2: raw partial.
// blockIdx.z = ((b*ocG + ocb)*KS + ks)
// ---------------------------------------------------------------------------
template <int TX, int EPI>
__global__ void __launch_bounds__(128)
conv5bf(const uint4* __restrict__ src0, int C0,
        const uint4* __restrict__ src1, int C1,
        const uint32_t* __restrict__ w, const float* __restrict__ bias,
        float* __restrict__ out, uint4* __restrict__ rhOut,
        int Cout, int H, int W, int ocG, int KS, int chunkIC)
{
    constexpr int TY = 8, IW = TX + 4, IH = TY + 4, IN = IH * IW;
    constexpr int SPAD = IN + ((4 - (IN % 16) + 16) % 16);  // SPAD % 16 == 4
    constexpr int PB = TX / 8;
    constexpr int NG = 2 * PB;
    constexpr int WN = 25 * 32 * 8;                          // 6400 u32 per buf

    extern __shared__ uint32_t smu[];
    uint4*    s_in = (uint4*)smu;          // [2][4][SPAD] uint4
    uint32_t* s_w  = smu + 32 * SPAD;      // [2][WN]

    int z = blockIdx.z;
    const int ks  = z % KS;  z /= KS;
    const int ocb = z % ocG;
    const int b   = z / ocG;
    const int y0  = blockIdx.y * TY;
    const int x0  = blockIdx.x * TX;
    const int tid  = threadIdx.x;
    const int warp = tid >> 5, lane = tid & 31;
    const int gid  = lane >> 2, tig = lane & 3;

    const int Cin = C0 + C1;
    const long long HW = (long long)H * W;
    const int icBeg = ks * chunkIC;
    const int NC = chunkIC / 8;

    const uint32_t sIN = (uint32_t)__cvta_generic_to_shared(s_in);
    const uint32_t sWB = (uint32_t)__cvta_generic_to_shared(s_w);

    auto fillChunk = [&](int buf, int ck) {
        const int cs = icBeg + ck * 8;   // chunks never straddle the C0 boundary
        const uint4* pb = (cs < C0)
            ? src0 + ((long long)b * (C0 >> 1) + (cs >> 1)) * HW
            : src1 + ((long long)b * (C1 >> 1) + ((cs - C0) >> 1)) * HW;
        for (int idx = tid; idx < IN; idx += 128) {
            int rr = idx / IW, cc = idx - rr * IW;
            int iy = y0 - 2 + rr, ix = x0 - 2 + cc;
            bool ok = (iy >= 0) && (iy < H) && (ix >= 0) && (ix < W);
            const uint4* g = ok ? (pb + (long long)iy * W + ix) : pb;
            uint32_t d = sIN + (uint32_t)(buf * 4 * SPAD + idx) * 16u;
#pragma unroll
            for (int t = 0; t < 4; t++)
                cp16(d + (uint32_t)(t * SPAD) * 16u, g + (long long)t * HW, ok);
        }
        for (int idx = tid; idx < WN; idx += 128) {
            // word = khkw*256 + tl*128 + (oc16*4 + t)*2 + half ; oc = tl*16+oc16, ic = t+4*half
            int khkw = idx >> 8;
            int rem  = idx & 255;
            int tl   = rem >> 7;
            int r2   = rem & 127;
            int oc16 = r2 >> 3;
            int t    = (r2 >> 1) & 3;
            int half = r2 & 1;
            int oc = tl * 16 + oc16;
            int ic = t + 4 * half;
            const uint32_t* g = w + ((long long)(ocb * 32 + oc) * Cin + (cs + ic)) * 25 + khkw;
            cp4(sWB + (uint32_t)(buf * WN + idx) * 4u, g, true);
        }
    };

    float acc[NG][2][4];
#pragma unroll
    for (int g = 0; g < NG; g++)
#pragma unroll
        for (int tl = 0; tl < 2; tl++)
#pragma unroll
            for (int j = 0; j < 4; j++) acc[g][tl][j] = 0.0f;

    fillChunk(0, 0);
    cpCommit();

    for (int ck = 0; ck < NC; ck++) {
        const int cur = ck & 1;
        if (ck + 1 < NC) fillChunk(cur ^ 1, ck + 1);
        cpCommit();
        cpWait<1>();
        __syncthreads();

        const uint4*    siT = s_in + cur * 4 * SPAD + tig * SPAD;
        const uint32_t* swB = s_w + cur * WN;
        const int prow = 2 * warp;

#pragma unroll
        for (int kh = 0; kh < 5; kh++) {
#pragma unroll
            for (int kw = 0; kw < 5; kw++) {
                const uint32_t* swk = swB + (kh * 5 + kw) * 256;
                uint2 a0[2], a1[2];
#pragma unroll
                for (int tl = 0; tl < 2; tl++) {
                    a0[tl] = *(const uint2*)(swk + tl * 128 + (gid * 4 + tig) * 2);
                    a1[tl] = *(const uint2*)(swk + tl * 128 + ((gid + 8) * 4 + tig) * 2);
                }
#pragma unroll
                for (int g = 0; g < NG; g++) {
                    const int r = g / PB, pb2 = g % PB;
                    const int px = (prow + r + kh) * IW + 8 * pb2 + gid + kw;
                    uint4 bb = siT[px];
#pragma unroll
                    for (int tl = 0; tl < 2; tl++) {
                        mma16(acc[g][tl], a0[tl].x, a1[tl].x, a0[tl].y, a1[tl].y, bb.x, bb.y);
                        mma16(acc[g][tl], a0[tl].x, a1[tl].x, a0[tl].y, a1[tl].y, bb.z, bb.w);
                    }
                }
            }
        }
        __syncthreads();
    }

    // epilogue: d0:(m=gid, x+0) d1:(gid, x+1) d2:(gid+8, x+0) d3:(gid+8, x+1)
#pragma unroll
    for (int g = 0; g < NG; g++) {
        const int r = g / PB, pb2 = g % PB;
        const int y = y0 + 2 * warp + r;
        const int xb = x0 + 8 * pb2 + 2 * tig;
#pragma unroll
        for (int tl = 0; tl < 2; tl++) {
#pragma unroll
            for (int j = 0; j < 4; j++) {
                const int m = gid + ((j >> 1) << 3);
                const int x = xb + (j & 1);
                const int c = ocb * 32 + tl * 16 + m;
                const long long pix = (long long)y * W + x;
                float v = acc[g][tl][j];
                if (EPI == 0) {
                    float a = v + bias[c];
                    float s = 1.0f / (1.0f + expf(-a));
                    out[((long long)b * Cout + c) * HW + pix] = s;
                    const int Ch = Cout >> 1;
                    if (c >= Ch) {
                        int hc = c - Ch;
                        const uint4* hp = src1 + (long long)b * (C1 >> 1) * HW;
                        float hv = loadSplit(hp, hc, HW, pix);
                        uint4* rp = rhOut + (long long)b * (C1 >> 1) * HW;
                        storeSplit(rp, hc, HW, pix, s * hv);
                    }
                } else {
                    out[((long long)(ks * BATCH + b) * Cout + c) * HW + pix] = v;
                }
            }
        }
    }
}

// ---------------------------------------------------------------------------
// Split-K epilogues
// ---------------------------------------------------------------------------
__global__ void zrEpiK(const float* __restrict__ part, int KS,
                       const float* __restrict__ bias, const float* __restrict__ hprevFp,
                       float* __restrict__ zrOut, uint4* __restrict__ rhSp,
                       int C2, long long HW)
{
    const long long n = (long long)BATCH * C2 * HW;
    long long i = (long long)blockIdx.x * blockDim.x + threadIdx.x;
    if (i >= n) return;
    float s = 0.0f;
    for (int k = 0; k < KS; k++) s += part[(long long)k * n + i];
    const int c = (int)((i / HW) % C2);
    s += bias[c];
    float sg = 1.0f / (1.0f + expf(-s));
    zrOut[i] = sg;
    const int C = C2 >> 1;
    if (c >= C) {
        long long b = i / (HW * C2);
        long long pix = i % HW;
        int hc = c - C;
        float rv = sg * hprevFp[(b * C + hc) * HW + pix];
        storeSplit(rhSp + b * (C >> 1) * HW, hc, HW, pix, rv);
    }
}

__global__ void hEpiK(const float* __restrict__ part, int KS,
                      const float* __restrict__ bias, const float* __restrict__ zr,
                      const float* __restrict__ hprevFp,
                      float* __restrict__ outFp, uint4* __restrict__ outSp,
                      int C, long long HW)
{
    const long long n = (long long)BATCH * C * HW;
    long long i = (long long)blockIdx.x * blockDim.x + threadIdx.x;
    if (i >= n) return;
    float s = 0.0f;
    for (int k = 0; k < KS; k++) s += part[(long long)k * n + i];
    const int c = (int)((i / HW) % C);
    long long b = i / (HW * C);
    long long pix = i % HW;
    float a = s + bias[c];
    float zv = zr[(b * (2 * C) + c) * HW + pix];
    float hp = hprevFp[i];
    float res = (1.0f - zv) * hp + zv * tanhf(a);
    outFp[i] = res;
    storeSplit(outSp + b * (C >> 1) * HW, c, HW, pix, res);
}

// ---------------------------------------------------------------------------

extern "C" void kernel_launch(void* const* d_in, const int* in_sizes, int n_in,
                              void* d_out, int out_size)
{
    const float* input   = (const float*)d_in[0];
    const float* c1_w    = (const float*)d_in[1];
    const float* c1_b    = (const float*)d_in[2];
    const float* g1_zr_w = (const float*)d_in[3];
    const float* g1_zr_b = (const float*)d_in[4];
    const float* g1_h_w  = (const float*)d_in[5];
    const float* g1_h_b  = (const float*)d_in[6];
    const float* c2_w    = (const float*)d_in[7];
    const float* c2_b    = (const float*)d_in[8];
    const float* g2_zr_w = (const float*)d_in[9];
    const float* g2_zr_b = (const float*)d_in[10];
    const float* g2_h_w  = (const float*)d_in[11];
    const float* g2_h_b  = (const float*)d_in[12];
    const float* c3_w    = (const float*)d_in[13];
    const float* c3_b    = (const float*)d_in[14];
    const float* g3_zr_w = (const float*)d_in[15];
    const float* g3_zr_b = (const float*)d_in[16];
    const float* g3_h_w  = (const float*)d_in[17];
    const float* g3_h_b  = (const float*)d_in[18];

    float *seq1, *seq2, *h3a, *h3b, *zr, *part, *zero0;
    uint4 *xsp1, *xsp2, *xsp3, *hsp1a, *hsp1b, *hsp2a, *hsp2b, *hsp3a, *hsp3b, *rhsp, *zsp;
    uint32_t* wc;
    cudaGetSymbolAddress((void**)&seq1,  g_seq1);
    cudaGetSymbolAddress((void**)&seq2,  g_seq2);
    cudaGetSymbolAddress((void**)&h3a,   g_h3a);
    cudaGetSymbolAddress((void**)&h3b,   g_h3b);
    cudaGetSymbolAddress((void**)&xsp1,  g_xsp1);
    cudaGetSymbolAddress((void**)&xsp2,  g_xsp2);
    cudaGetSymbolAddress((void**)&xsp3,  g_xsp3);
    cudaGetSymbolAddress((void**)&hsp1a, g_hsp1a);
    cudaGetSymbolAddress((void**)&hsp1b, g_hsp1b);
    cudaGetSymbolAddress((void**)&hsp2a, g_hsp2a);
    cudaGetSymbolAddress((void**)&hsp2b, g_hsp2b);
    cudaGetSymbolAddress((void**)&hsp3a, g_hsp3a);
    cudaGetSymbolAddress((void**)&hsp3b, g_hsp3b);
    cudaGetSymbolAddress((void**)&rhsp,  g_rhsp);
    cudaGetSymbolAddress((void**)&zr,    g_zr);
    cudaGetSymbolAddress((void**)&part,  g_part);
    cudaGetSymbolAddress((void**)&zero0, g_zero);
    cudaGetSymbolAddress((void**)&zsp,   g_zsp);
    cudaGetSymbolAddress((void**)&wc,    g_wcvt);

    // converted-weight offsets
    uint32_t* w1zr = wc;                 // 409600
    uint32_t* w1h  = wc + 409600;        // 204800
    uint32_t* w2zr = wc + 614400;        // 1638400
    uint32_t* w2h  = wc + 2252800;       // 819200
    uint32_t* w3zr = wc + 3072000;       // 1638400
    uint32_t* w3h  = wc + 4710400;       // 819200

    // smem sizes (input uint4 planes + 32-oc weight bufs)
    constexpr int IN32 = 12 * 36, SP32 = IN32 + ((4 - (IN32 % 16) + 16) % 16); // 436
    constexpr int IN16 = 12 * 20, SP16 = IN16 + ((4 - (IN16 % 16) + 16) % 16); // 244
    constexpr int WN2  = 2 * 25 * 32 * 8;                                       // 12800 u32
    constexpr int SM32 = (32 * SP32 + WN2) * 4;   // 107,008 B -> 2 blocks/SM
    constexpr int SM16 = (32 * SP16 + WN2) * 4;   //  82,432 B -> 2 blocks/SM
    cudaFuncSetAttribute(conv5bf<32, 0>, cudaFuncAttributeMaxDynamicSharedMemorySize, SM32);
    cudaFuncSetAttribute(conv5bf<32, 2>, cudaFuncAttributeMaxDynamicSharedMemorySize, SM32);
    cudaFuncSetAttribute(conv5bf<16, 2>, cudaFuncAttributeMaxDynamicSharedMemorySize, SM16);

    // per-launch weight conversion (deterministic, graph-capturable)
    wcvtK<<<(409600 + 255) / 256, 256>>>(g1_zr_w, w1zr, 409600);
    wcvtK<<<(204800 + 255) / 256, 256>>>(g1_h_w,  w1h,  204800);
    wcvtK<<<(1638400 + 255) / 256, 256>>>(g2_zr_w, w2zr, 1638400);
    wcvtK<<<(819200 + 255) / 256, 256>>>(g2_h_w,  w2h,  819200);
    wcvtK<<<(1638400 + 255) / 256, 256>>>(g3_zr_w, w3zr, 1638400);
    wcvtK<<<(819200 + 255) / 256, 256>>>(g3_h_w,  w3h,  819200);

    {   // zero h0 buffers (fp32 + split)
        int nz = BATCH * 64 * 64 * 64;
        int nz4 = BATCH * 32 * 64 * 64;
        zerok<<<(nz + 255) / 256, 256>>>(zero0, zsp, nz, nz4);
    }

    const size_t S1  = (size_t)BATCH * 64 * 64 * 64;
    const size_t S2  = (size_t)BATCH * 128 * 32 * 32;
    const size_t S1p = (size_t)BATCH * 32 * 64 * 64;
    const size_t S2p = (size_t)BATCH * 64 * 32 * 32;
    const size_t S3p = (size_t)BATCH * 64 * 16 * 16;

    // ================= Stage 1: 1 -> 64ch, 128x128 -> 64x64 =================
    conv4s2<16, 8, 8><<<dim3(4, 8, TSTEPS * BATCH * 8), dim3(16, 8)>>>(
        input, (long long)TSTEPS * 128 * 128, (long long)128 * 128,
        c1_w, c1_b, xsp1, 1, 64, 128, 128);

    {
        uint4* hspb[2] = { hsp1a, hsp1b };
        for (int t = 0; t < TSTEPS; t++) {
            const uint4* xt = xsp1 + (size_t)t * S1p;
            const uint4* hprevSp = t ? hspb[(t - 1) & 1] : zsp;
            const float* hprevFp = t ? seq1 + (size_t)(t - 1) * S1 : zero0;
            // zr fused (KS=1): Cout=128, ocG=4
            conv5bf<32, 0><<<dim3(2, 8, BATCH * 4), 128, SM32>>>(
                xt, 64, hprevSp, 64, w1zr, g1_zr_b, zr, rhsp, 128, 64, 64, 4, 1, 128);
            // h raw split-K=2: Cout=64, ocG=2
            conv5bf<32, 2><<<dim3(2, 8, BATCH * 2 * 2), 128, SM32>>>(
                xt, 64, rhsp, 64, w1h, nullptr, part, nullptr, 64, 64, 64, 2, 2, 64);
            long long n = (long long)BATCH * 64 * 4096;
            hEpiK<<<(unsigned)((n + 255) / 256), 256>>>(
                part, 2, g1_h_b, zr, hprevFp, seq1 + (size_t)t * S1, hspb[t & 1], 64, 4096);
        }
    }

    // ================= Stage 2: 64 -> 128ch, 64x64 -> 32x32 =================
    conv4s2<16, 8, 8><<<dim3(2, 4, TSTEPS * BATCH * 16), dim3(16, 8)>>>(
        seq1, (long long)64 * 4096, (long long)BATCH * 64 * 4096,
        c2_w, c2_b, xsp2, 64, 128, 64, 64);

    {
        uint4* hspb[2] = { hsp2a, hsp2b };
        for (int t = 0; t < TSTEPS; t++) {
            const uint4* xt = xsp2 + (size_t)t * S2p;
            const uint4* hprevSp = t ? hspb[(t - 1) & 1] : zsp;
            const float* hprevFp = t ? seq2 + (size_t)(t - 1) * S2 : zero0;
            // zr raw split-K=2: Cout=256, ocG=8
            conv5bf<32, 2><<<dim3(1, 4, BATCH * 8 * 2), 128, SM32>>>(
                xt, 128, hprevSp, 128, w2zr, nullptr, part, nullptr, 256, 32, 32, 8, 2, 128);
            {
                long long n = (long long)BATCH * 256 * 1024;
                zrEpiK<<<(unsigned)((n + 255) / 256), 256>>>(part, 2, g2_zr_b, hprevFp, zr, rhsp, 256, 1024);
            }
            // h raw split-K=4: Cout=128, ocG=4
            conv5bf<32, 2><<<dim3(1, 4, BATCH * 4 * 4), 128, SM32>>>(
                xt, 128, rhsp, 128, w2h, nullptr, part, nullptr, 128, 32, 32, 4, 4, 64);
            long long n = (long long)BATCH * 128 * 1024;
            hEpiK<<<(unsigned)((n + 255) / 256), 256>>>(
                part, 4, g2_h_b, zr, hprevFp, seq2 + (size_t)t * S2, hspb[t & 1], 128, 1024);
        }
    }

    // ================= Stage 3: 128 -> 128ch, 32x32 -> 16x16 ================
    conv4s2<16, 8, 8><<<dim3(1, 2, TSTEPS * BATCH * 16), dim3(16, 8)>>>(
        seq2, (long long)128 * 1024, (long long)BATCH * 128 * 1024,
        c3_w, c3_b, xsp3, 128, 128, 32, 32);

    float* h3final = nullptr;
    {
        uint4* hspb[2] = { hsp3a, hsp3b };
        float* hfp[2]  = { h3a, h3b };
        for (int t = 0; t < TSTEPS; t++) {
            const uint4* xt = xsp3 + (size_t)t * S3p;
            const uint4* hprevSp = t ? hspb[(t - 1) & 1] : zsp;
            const float* hprevFp = t ? hfp[(t - 1) & 1] : zero0;
            // zr raw split-K=4: Cout=256, ocG=8
            conv5bf<16, 2><<<dim3(1, 2, BATCH * 8 * 4), 128, SM16>>>(
                xt, 128, hprevSp, 128, w3zr, nullptr, part, nullptr, 256, 16, 16, 8, 4, 64);
            {
                long long n = (long long)BATCH * 256 * 256;
                zrEpiK<<<(unsigned)((n + 255) / 256), 256>>>(part, 4, g3_zr_b, hprevFp, zr, rhsp, 256, 256);
            }
            // h raw split-K=8: Cout=128, ocG=4
            conv5bf<16, 2><<<dim3(1, 2, BATCH * 4 * 8), 128, SM16>>>(
                xt, 128, rhsp, 128, w3h, nullptr, part, nullptr, 128, 16, 16, 4, 8, 32);
            long long n = (long long)BATCH * 128 * 256;
            hEpiK<<<(unsigned)((n + 255) / 256), 256>>>(
                part, 8, g3_h_b, zr, hprevFp, hfp[t & 1], hspb[t & 1], 128, 256);
            h3final = hfp[t & 1];
        }
    }

    // ================= Gather outputs =================
    float* out = (float*)d_out;
    int n1 = (int)S1, n2 = (int)S2, n3 = BATCH * 128 * 16 * 16;
    copyk<<<(n1 + 255) / 256, 256>>>(out, seq1 + (size_t)(TSTEPS - 1) * S1, n1);
    copyk<<<(n2 + 255) / 256, 256>>>(out + n1, seq2 + (size_t)(TSTEPS - 1) * S2, n2);
    copyk<<<(n3 + 255) / 256, 256>>>(out + n1 + n2, h3final, n3);
}

// round 10
// speedup vs baseline: 1.0506x; 1.0506x over previous
#include <cuda_runtime.h>
#include <cuda_bf16.h>
#include <math.h>
#include <stdint.h>

#define TSTEPS 12
#define BATCH  8

// ---------------- scratch (static device globals) ---------------------------
__device__ float  g_seq1[(size_t)TSTEPS * BATCH * 64 * 64 * 64];
__device__ float  g_seq2[(size_t)TSTEPS * BATCH * 128 * 32 * 32];
__device__ float  g_h3a [(size_t)BATCH * 128 * 16 * 16];
__device__ float  g_h3b [(size_t)BATCH * 128 * 16 * 16];
// bf16-split activations: uint4 per CHANNEL-PAIR per pixel:
//  .x = dup(hi(ch c)), .y = dup(hi(ch c+4)), .z = dup(lo(ch c)), .w = dup(lo(ch c+4))
//  plane index for channel c: (c>>3)*4 + (c&3); slot = (c>>2)&1
__device__ uint4  g_xsp1[(size_t)TSTEPS * BATCH * 32 * 64 * 64];
__device__ uint4  g_xsp2[(size_t)TSTEPS * BATCH * 64 * 32 * 32];
__device__ uint4  g_xsp3[(size_t)TSTEPS * BATCH * 64 * 16 * 16];
__device__ uint4  g_hsp1a[(size_t)BATCH * 32 * 64 * 64];
__device__ uint4  g_hsp1b[(size_t)BATCH * 32 * 64 * 64];
__device__ uint4  g_hsp2a[(size_t)BATCH * 64 * 32 * 32];
__device__ uint4  g_hsp2b[(size_t)BATCH * 64 * 32 * 32];
__device__ uint4  g_hsp3a[(size_t)BATCH * 64 * 16 * 16];
__device__ uint4  g_hsp3b[(size_t)BATCH * 64 * 16 * 16];
__device__ uint4  g_rhsp[(size_t)BATCH * 32 * 64 * 64];
__device__ uint4  g_zsp [(size_t)BATCH * 32 * 64 * 64];
__device__ float  g_zr  [(size_t)BATCH * 128 * 64 * 64];
__device__ float  g_part[(size_t)8388608];
__device__ float  g_zero[(size_t)BATCH * 64 * 64 * 64];
// packed bf16x2 weights (low16 = wHi, high16 = wLo), fp32 weight indexing
__device__ uint32_t g_wcvt[(size_t)5529600];

// ---------------- bf16 split helpers ----------------------------------------
__device__ __forceinline__ void bsplit(float v, uint16_t& hb, uint16_t& lb) {
    __nv_bfloat16 h = __float2bfloat16(v);
    float hf = __bfloat162float(h);
    __nv_bfloat16 l = __float2bfloat16(v - hf);
    hb = __bfloat16_as_ushort(h);
    lb = __bfloat16_as_ushort(l);
}
__device__ __forceinline__ uint32_t dup16(uint16_t b) {
    return ((uint32_t)b << 16) | (uint32_t)b;
}
__device__ __forceinline__ void storeSplit(uint4* planeBase, int c, long long HW,
                                           long long pix, float v) {
    uint16_t hb, lb;
    bsplit(v, hb, lb);
    uint32_t* p = (uint32_t*)(planeBase + (long long)((c >> 3) * 4 + (c & 3)) * HW + pix);
    int slot = (c >> 2) & 1;
    p[slot] = dup16(hb);
    p[2 + slot] = dup16(lb);
}
__device__ __forceinline__ float loadSplit(const uint4* planeBase, int c, long long HW,
                                           long long pix) {
    const uint32_t* p = (const uint32_t*)(planeBase + (long long)((c >> 3) * 4 + (c & 3)) * HW + pix);
    int slot = (c >> 2) & 1;
    return __bfloat162float(__ushort_as_bfloat16((uint16_t)p[slot])) +
           __bfloat162float(__ushort_as_bfloat16((uint16_t)p[2 + slot]));
}

__global__ void zerok(float* p, uint4* p2, int n, int n2) {
    int i = blockIdx.x * blockDim.x + threadIdx.x;
    if (i < n) p[i] = 0.0f;
    if (i < n2) p2[i] = make_uint4(0, 0, 0, 0);
}
__global__ void copyk(float* __restrict__ dst, const float* __restrict__ src, int n) {
    int i = blockIdx.x * blockDim.x + threadIdx.x;
    if (i < n) dst[i] = src[i];
}
__global__ void wcvtK(const float* __restrict__ w, uint32_t* __restrict__ o, int n) {
    int i = blockIdx.x * blockDim.x + threadIdx.x;
    if (i >= n) return;
    uint16_t hb, lb;
    bsplit(w[i], hb, lb);
    o[i] = ((uint32_t)lb << 16) | (uint32_t)hb;
}

// ---------------- cp.async helpers ------------------------------------------
__device__ __forceinline__ void cp4(uint32_t saddr, const void* g, bool ok) {
    int sz = ok ? 4 : 0;
    asm volatile("cp.async.ca.shared.global [%0], [%1], 4, %2;\n"
                 :: "r"(saddr), "l"(g), "r"(sz));
}
__device__ __forceinline__ void cp16(uint32_t saddr, const void* g, bool ok) {
    int sz = ok ? 16 : 0;
    asm volatile("cp.async.cg.shared.global [%0], [%1], 16, %2;\n"
                 :: "r"(saddr), "l"(g), "r"(sz));
}
__device__ __forceinline__ void cpCommit() {
    asm volatile("cp.async.commit_group;\n" ::: "memory");
}
template <int N>
__device__ __forceinline__ void cpWait() {
    asm volatile("cp.async.wait_group %0;\n" :: "n"(N) : "memory");
}
__device__ __forceinline__ void mma16(float* d, uint32_t a0, uint32_t a1, uint32_t a2,
                                      uint32_t a3, uint32_t b0, uint32_t b1) {
    asm volatile(
        "mma.sync.aligned.m16n8k16.row.col.f32.bf16.bf16.f32 "
        "{%0,%1,%2,%3}, {%4,%5,%6,%7}, {%8,%9}, {%0,%1,%2,%3};"
        : "+f"(d[0]), "+f"(d[1]), "+f"(d[2]), "+f"(d[3])
        : "r"(a0), "r"(a1), "r"(a2), "r"(a3), "r"(b0), "r"(b1));
}

// ---------------------------------------------------------------------------
// Strided conv k4 s2 p1, batched over T. Output written bf16-SPLIT (uint4 planes).
// ---------------------------------------------------------------------------
template <int TX, int TY, int OC>
__global__ void conv4s2(const float* __restrict__ in,
                        long long strideB, long long strideT,
                        const float* __restrict__ w, const float* __restrict__ bias,
                        uint4* __restrict__ out,
                        int Cin, int Cout, int Hin, int Win)
{
    const int Hout = Hin >> 1, Wout = Win >> 1;
    const int ocG = Cout / OC;
    int z = blockIdx.z;
    const int ocb = z % ocG; z /= ocG;
    const int b   = z % BATCH;
    const int t   = z / BATCH;
    const int y0  = blockIdx.y * TY;
    const int x0  = blockIdx.x * TX;

    constexpr int IW = 2 * TX + 2;
    constexpr int IH = 2 * TY + 2;
    __shared__ float s_in[IH * IW];
    __shared__ float s_w[OC * 16];

    const int tid = threadIdx.y * TX + threadIdx.x;
    const int nth = TX * TY;
    const float* base = in + (long long)b * strideB + (long long)t * strideT;

    float acc[OC];
#pragma unroll
    for (int oc = 0; oc < OC; oc++) acc[oc] = 0.0f;

    for (int ic = 0; ic < Cin; ic++) {
        const float* src = base + (long long)ic * Hin * Win;
        for (int idx = tid; idx < IH * IW; idx += nth) {
            int iy = 2 * y0 - 1 + idx / IW;
            int ix = 2 * x0 - 1 + idx % IW;
            s_in[idx] = (iy >= 0 && iy < Hin && ix >= 0 && ix < Win)
                            ? src[(long long)iy * Win + ix] : 0.0f;
        }
        for (int idx = tid; idx < OC * 16; idx += nth) {
            int oc = idx / 16, k = idx % 16;
            s_w[idx] = w[(((long long)(ocb * OC + oc)) * Cin + ic) * 16 + k];
        }
        __syncthreads();
#pragma unroll
        for (int kh = 0; kh < 4; kh++)
#pragma unroll
            for (int kw = 0; kw < 4; kw++) {
                float inv = s_in[(2 * threadIdx.y + kh) * IW + 2 * threadIdx.x + kw];
#pragma unroll
                for (int oc = 0; oc < OC; oc++)
                    acc[oc] = fmaf(inv, s_w[oc * 16 + kh * 4 + kw], acc[oc]);
            }
        __syncthreads();
    }

    const int y = y0 + threadIdx.y, x = x0 + threadIdx.x;
    const long long HWo = (long long)Hout * Wout;
    uint4* ob = out + (long long)(t * BATCH + b) * (Cout >> 1) * HWo;
#pragma unroll
    for (int oc = 0; oc < 4; oc++) {
        int c0 = ocb * OC + oc;
        uint16_t h0, l0, h1, l1;
        bsplit(acc[oc] + bias[c0], h0, l0);
        bsplit(acc[oc + 4] + bias[c0 + 4], h1, l1);
        ob[(long long)(ocb * 4 + oc) * HWo + (long long)y * Wout + x]
            = make_uint4(dup16(h0), dup16(h1), dup16(l0), dup16(l1));
    }
}

// ---------------------------------------------------------------------------
// 5x5 conv s1 p2, implicit GEMM, split-BF16 mma.sync.m16n8k16.
// Block 128 thr (4 warps). Tile: TX x 8 px rows, 16 output channels (R8 tile).
// B fragment = ONE LDS.128 of the producer's native uint4 (hh0,hh1,ll0,ll1):
// hi-MMA uses (.x,.y), lo-MMA uses (.z,.w). 2 MMAs per tap per px-group.
// smem: input [2buf][4 pair-planes][SPAD] uint4; weights [2buf][25][16oc][4t][2half].
// EPI 0: fused sigmoid -> zr fp32 + rh split (KS must be 1). EPI 2: raw partial.
// blockIdx.z = ((b*ocG + ocb)*KS + ks)
// ---------------------------------------------------------------------------
template <int TX, int EPI>
__global__ void __launch_bounds__(128)
conv5bf(const uint4* __restrict__ src0, int C0,
        const uint4* __restrict__ src1, int C1,
        const uint32_t* __restrict__ w, const float* __restrict__ bias,
        float* __restrict__ out, uint4* __restrict__ rhOut,
        int Cout, int H, int W, int ocG, int KS, int chunkIC)
{
    constexpr int TY = 8, IW = TX + 4, IH = TY + 4, IN = IH * IW;
    constexpr int SPAD = IN + ((4 - (IN % 16) + 16) % 16);  // SPAD % 16 == 4
    constexpr int PB = TX / 8;
    constexpr int NG = 2 * PB;
    constexpr int WN = 25 * 16 * 4 * 2;                      // 3200 u32 per buf

    extern __shared__ uint32_t smu[];
    uint4*    s_in = (uint4*)smu;          // [2][4][SPAD] uint4
    uint32_t* s_w  = smu + 32 * SPAD;      // [2][WN]

    int z = blockIdx.z;
    const int ks  = z % KS;  z /= KS;
    const int ocb = z % ocG;
    const int b   = z / ocG;
    const int y0  = blockIdx.y * TY;
    const int x0  = blockIdx.x * TX;
    const int tid  = threadIdx.x;
    const int warp = tid >> 5, lane = tid & 31;
    const int gid  = lane >> 2, tig = lane & 3;

    const int Cin = C0 + C1;
    const long long HW = (long long)H * W;
    const int icBeg = ks * chunkIC;
    const int NC = chunkIC / 8;

    const uint32_t sIN = (uint32_t)__cvta_generic_to_shared(s_in);
    const uint32_t sWB = (uint32_t)__cvta_generic_to_shared(s_w);

    auto fillChunk = [&](int buf, int ck) {
        const int cs = icBeg + ck * 8;   // chunks never straddle the C0 boundary
        const uint4* pb = (cs < C0)
            ? src0 + ((long long)b * (C0 >> 1) + (cs >> 1)) * HW
            : src1 + ((long long)b * (C1 >> 1) + ((cs - C0) >> 1)) * HW;
        for (int idx = tid; idx < IN; idx += 128) {
            int rr = idx / IW, cc = idx - rr * IW;
            int iy = y0 - 2 + rr, ix = x0 - 2 + cc;
            bool ok = (iy >= 0) && (iy < H) && (ix >= 0) && (ix < W);
            const uint4* g = ok ? (pb + (long long)iy * W + ix) : pb;
            uint32_t d = sIN + (uint32_t)(buf * 4 * SPAD + idx) * 16u;
#pragma unroll
            for (int t = 0; t < 4; t++)
                cp16(d + (uint32_t)(t * SPAD) * 16u, g + (long long)t * HW, ok);
        }
        for (int idx = tid; idx < WN; idx += 128) {
            // word = ((khkw*16 + oc)*4 + t)*2 + half ; ic = t + 4*half
            int half = idx & 1;
            int t    = (idx >> 1) & 3;
            int oc   = (idx >> 3) & 15;
            int khkw = idx >> 7;
            int ic = t + 4 * half;
            const uint32_t* g = w + ((long long)(ocb * 16 + oc) * Cin + (cs + ic)) * 25 + khkw;
            cp4(sWB + (uint32_t)(buf * WN + idx) * 4u, g, true);
        }
    };

    float acc[NG][4];
#pragma unroll
    for (int g = 0; g < NG; g++)
#pragma unroll
        for (int j = 0; j < 4; j++) acc[g][j] = 0.0f;

    fillChunk(0, 0);
    cpCommit();

    for (int ck = 0; ck < NC; ck++) {
        const int cur = ck & 1;
        if (ck + 1 < NC) fillChunk(cur ^ 1, ck + 1);
        cpCommit();
        cpWait<1>();
        __syncthreads();

        const uint4*    siT = s_in + cur * 4 * SPAD + tig * SPAD;
        const uint32_t* swB = s_w + cur * WN;
        const int prow = 2 * warp;

#pragma unroll
        for (int kh = 0; kh < 5; kh++) {
#pragma unroll
            for (int kw = 0; kw < 5; kw++) {
                const uint32_t* swk = swB + (kh * 5 + kw) * 128;
                uint2 aP0 = *(const uint2*)(swk + (gid * 4 + tig) * 2);        // a0,a2
                uint2 aP1 = *(const uint2*)(swk + ((gid + 8) * 4 + tig) * 2);  // a1,a3
#pragma unroll
                for (int g = 0; g < NG; g++) {
                    const int r = g / PB, pb2 = g % PB;
                    const int px = (prow + r + kh) * IW + 8 * pb2 + gid + kw;
                    uint4 bb = siT[px];
                    mma16(acc[g], aP0.x, aP1.x, aP0.y, aP1.y, bb.x, bb.y);
                    mma16(acc[g], aP0.x, aP1.x, aP0.y, aP1.y, bb.z, bb.w);
                }
            }
        }
        __syncthreads();
    }

    // epilogue: d0:(m=gid, x+0) d1:(gid, x+1) d2:(gid+8, x+0) d3:(gid+8, x+1)
#pragma unroll
    for (int g = 0; g < NG; g++) {
        const int r = g / PB, pb2 = g % PB;
        const int y = y0 + 2 * warp + r;
        const int xb = x0 + 8 * pb2 + 2 * tig;
#pragma unroll
        for (int j = 0; j < 4; j++) {
            const int m = gid + ((j >> 1) << 3);
            const int x = xb + (j & 1);
            const int c = ocb * 16 + m;
            const long long pix = (long long)y * W + x;
            float v = acc[g][j];
            if (EPI == 0) {
                float a = v + bias[c];
                float s = 1.0f / (1.0f + expf(-a));
                out[((long long)b * Cout + c) * HW + pix] = s;
                const int Ch = Cout >> 1;
                if (c >= Ch) {
                    int hc = c - Ch;
                    const uint4* hp = src1 + (long long)b * (C1 >> 1) * HW;
                    float hv = loadSplit(hp, hc, HW, pix);
                    uint4* rp = rhOut + (long long)b * (C1 >> 1) * HW;
                    storeSplit(rp, hc, HW, pix, s * hv);
                }
            } else {
                out[((long long)(ks * BATCH + b) * Cout + c) * HW + pix] = v;
            }
        }
    }
}

// ---------------------------------------------------------------------------
// Split-K epilogues
// ---------------------------------------------------------------------------
__global__ void zrEpiK(const float* __restrict__ part, int KS,
                       const float* __restrict__ bias, const float* __restrict__ hprevFp,
                       float* __restrict__ zrOut, uint4* __restrict__ rhSp,
                       int C2, long long HW)
{
    const long long n = (long long)BATCH * C2 * HW;
    long long i = (long long)blockIdx.x * blockDim.x + threadIdx.x;
    if (i >= n) return;
    float s = 0.0f;
    for (int k = 0; k < KS; k++) s += part[(long long)k * n + i];
    const int c = (int)((i / HW) % C2);
    s += bias[c];
    float sg = 1.0f / (1.0f + expf(-s));
    zrOut[i] = sg;
    const int C = C2 >> 1;
    if (c >= C) {
        long long b = i / (HW * C2);
        long long pix = i % HW;
        int hc = c - C;
        float rv = sg * hprevFp[(b * C + hc) * HW + pix];
        storeSplit(rhSp + b * (C >> 1) * HW, hc, HW, pix, rv);
    }
}

__global__ void hEpiK(const float* __restrict__ part, int KS,
                      const float* __restrict__ bias, const float* __restrict__ zr,
                      const float* __restrict__ hprevFp,
                      float* __restrict__ outFp, uint4* __restrict__ outSp,
                      int C, long long HW)
{
    const long long n = (long long)BATCH * C * HW;
    long long i = (long long)blockIdx.x * blockDim.x + threadIdx.x;
    if (i >= n) return;
    float s = 0.0f;
    for (int k = 0; k < KS; k++) s += part[(long long)k * n + i];
    const int c = (int)((i / HW) % C);
    long long b = i / (HW * C);
    long long pix = i % HW;
    float a = s + bias[c];
    float zv = zr[(b * (2 * C) + c) * HW + pix];
    float hp = hprevFp[i];
    float res = (1.0f - zv) * hp + zv * tanhf(a);
    outFp[i] = res;
    storeSplit(outSp + b * (C >> 1) * HW, c, HW, pix, res);
}

// ---------------------------------------------------------------------------

extern "C" void kernel_launch(void* const* d_in, const int* in_sizes, int n_in,
                              void* d_out, int out_size)
{
    const float* input   = (const float*)d_in[0];
    const float* c1_w    = (const float*)d_in[1];
    const float* c1_b    = (const float*)d_in[2];
    const float* g1_zr_w = (const float*)d_in[3];
    const float* g1_zr_b = (const float*)d_in[4];
    const float* g1_h_w  = (const float*)d_in[5];
    const float* g1_h_b  = (const float*)d_in[6];
    const float* c2_w    = (const float*)d_in[7];
    const float* c2_b    = (const float*)d_in[8];
    const float* g2_zr_w = (const float*)d_in[9];
    const float* g2_zr_b = (const float*)d_in[10];
    const float* g2_h_w  = (const float*)d_in[11];
    const float* g2_h_b  = (const float*)d_in[12];
    const float* c3_w    = (const float*)d_in[13];
    const float* c3_b    = (const float*)d_in[14];
    const float* g3_zr_w = (const float*)d_in[15];
    const float* g3_zr_b = (const float*)d_in[16];
    const float* g3_h_w  = (const float*)d_in[17];
    const float* g3_h_b  = (const float*)d_in[18];

    float *seq1, *seq2, *h3a, *h3b, *zr, *part, *zero0;
    uint4 *xsp1, *xsp2, *xsp3, *hsp1a, *hsp1b, *hsp2a, *hsp2b, *hsp3a, *hsp3b, *rhsp, *zsp;
    uint32_t* wc;
    cudaGetSymbolAddress((void**)&seq1,  g_seq1);
    cudaGetSymbolAddress((void**)&seq2,  g_seq2);
    cudaGetSymbolAddress((void**)&h3a,   g_h3a);
    cudaGetSymbolAddress((void**)&h3b,   g_h3b);
    cudaGetSymbolAddress((void**)&xsp1,  g_xsp1);
    cudaGetSymbolAddress((void**)&xsp2,  g_xsp2);
    cudaGetSymbolAddress((void**)&xsp3,  g_xsp3);
    cudaGetSymbolAddress((void**)&hsp1a, g_hsp1a);
    cudaGetSymbolAddress((void**)&hsp1b, g_hsp1b);
    cudaGetSymbolAddress((void**)&hsp2a, g_hsp2a);
    cudaGetSymbolAddress((void**)&hsp2b, g_hsp2b);
    cudaGetSymbolAddress((void**)&hsp3a, g_hsp3a);
    cudaGetSymbolAddress((void**)&hsp3b, g_hsp3b);
    cudaGetSymbolAddress((void**)&rhsp,  g_rhsp);
    cudaGetSymbolAddress((void**)&zr,    g_zr);
    cudaGetSymbolAddress((void**)&part,  g_part);
    cudaGetSymbolAddress((void**)&zero0, g_zero);
    cudaGetSymbolAddress((void**)&zsp,   g_zsp);
    cudaGetSymbolAddress((void**)&wc,    g_wcvt);

    // converted-weight offsets
    uint32_t* w1zr = wc;                 // 409600
    uint32_t* w1h  = wc + 409600;        // 204800
    uint32_t* w2zr = wc + 614400;        // 1638400
    uint32_t* w2h  = wc + 2252800;       // 819200
    uint32_t* w3zr = wc + 3072000;       // 1638400
    uint32_t* w3h  = wc + 4710400;       // 819200

    // smem sizes (same footprint as R8)
    constexpr int IN32 = 12 * 36, SP32 = IN32 + ((4 - (IN32 % 16) + 16) % 16); // 436
    constexpr int IN16 = 12 * 20, SP16 = IN16 + ((4 - (IN16 % 16) + 16) % 16); // 244
    constexpr int WN2  = 2 * 25 * 16 * 4 * 2;                                   // 6400 u32
    constexpr int SM32 = (32 * SP32 + WN2) * 4;   // 81,408 B
    constexpr int SM16 = (32 * SP16 + WN2) * 4;   // 56,832 B
    cudaFuncSetAttribute(conv5bf<32, 0>, cudaFuncAttributeMaxDynamicSharedMemorySize, SM32);
    cudaFuncSetAttribute(conv5bf<32, 2>, cudaFuncAttributeMaxDynamicSharedMemorySize, SM32);
    cudaFuncSetAttribute(conv5bf<16, 2>, cudaFuncAttributeMaxDynamicSharedMemorySize, SM16);

    // per-launch weight conversion (deterministic, graph-capturable)
    wcvtK<<<(409600 + 255) / 256, 256>>>(g1_zr_w, w1zr, 409600);
    wcvtK<<<(204800 + 255) / 256, 256>>>(g1_h_w,  w1h,  204800);
    wcvtK<<<(1638400 + 255) / 256, 256>>>(g2_zr_w, w2zr, 1638400);
    wcvtK<<<(819200 + 255) / 256, 256>>>(g2_h_w,  w2h,  819200);
    wcvtK<<<(1638400 + 255) / 256, 256>>>(g3_zr_w, w3zr, 1638400);
    wcvtK<<<(819200 + 255) / 256, 256>>>(g3_h_w,  w3h,  819200);

    {   // zero h0 buffers (fp32 + split)
        int nz = BATCH * 64 * 64 * 64;
        int nz4 = BATCH * 32 * 64 * 64;
        zerok<<<(nz + 255) / 256, 256>>>(zero0, zsp, nz, nz4);
    }

    const size_t S1  = (size_t)BATCH * 64 * 64 * 64;
    const size_t S2  = (size_t)BATCH * 128 * 32 * 32;
    const size_t S1p = (size_t)BATCH * 32 * 64 * 64;
    const size_t S2p = (size_t)BATCH * 64 * 32 * 32;
    const size_t S3p = (size_t)BATCH * 64 * 16 * 16;

    // ================= Stage 1: 1 -> 64ch, 128x128 -> 64x64 =================
    conv4s2<16, 8, 8><<<dim3(4, 8, TSTEPS * BATCH * 8), dim3(16, 8)>>>(
        input, (long long)TSTEPS * 128 * 128, (long long)128 * 128,
        c1_w, c1_b, xsp1, 1, 64, 128, 128);

    {
        uint4* hspb[2] = { hsp1a, hsp1b };
        for (int t = 0; t < TSTEPS; t++) {
            const uint4* xt = xsp1 + (size_t)t * S1p;
            const uint4* hprevSp = t ? hspb[(t - 1) & 1] : zsp;
            const float* hprevFp = t ? seq1 + (size_t)(t - 1) * S1 : zero0;
            // zr fused (KS=1): Cout=128, ocG=8
            conv5bf<32, 0><<<dim3(2, 8, BATCH * 8), 128, SM32>>>(
                xt, 64, hprevSp, 64, w1zr, g1_zr_b, zr, rhsp, 128, 64, 64, 8, 1, 128);
            // h raw split-K=2: Cout=64, ocG=4
            conv5bf<32, 2><<<dim3(2, 8, BATCH * 4 * 2), 128, SM32>>>(
                xt, 64, rhsp, 64, w1h, nullptr, part, nullptr, 64, 64, 64, 4, 2, 64);
            long long n = (long long)BATCH * 64 * 4096;
            hEpiK<<<(unsigned)((n + 255) / 256), 256>>>(
                part, 2, g1_h_b, zr, hprevFp, seq1 + (size_t)t * S1, hspb[t & 1], 64, 4096);
        }
    }

    // ================= Stage 2: 64 -> 128ch, 64x64 -> 32x32 =================
    conv4s2<16, 8, 8><<<dim3(2, 4, TSTEPS * BATCH * 16), dim3(16, 8)>>>(
        seq1, (long long)64 * 4096, (long long)BATCH * 64 * 4096,
        c2_w, c2_b, xsp2, 64, 128, 64, 64);

    {
        uint4* hspb[2] = { hsp2a, hsp2b };
        for (int t = 0; t < TSTEPS; t++) {
            const uint4* xt = xsp2 + (size_t)t * S2p;
            const uint4* hprevSp = t ? hspb[(t - 1) & 1] : zsp;
            const float* hprevFp = t ? seq2 + (size_t)(t - 1) * S2 : zero0;
            // zr raw split-K=2: Cout=256, ocG=16
            conv5bf<32, 2><<<dim3(1, 4, BATCH * 16 * 2), 128, SM32>>>(
                xt, 128, hprevSp, 128, w2zr, nullptr, part, nullptr, 256, 32, 32, 16, 2, 128);
            {
                long long n = (long long)BATCH * 256 * 1024;
                zrEpiK<<<(unsigned)((n + 255) / 256), 256>>>(part, 2, g2_zr_b, hprevFp, zr, rhsp, 256, 1024);
            }
            // h raw split-K=4: Cout=128, ocG=8
            conv5bf<32, 2><<<dim3(1, 4, BATCH * 8 * 4), 128, SM32>>>(
                xt, 128, rhsp, 128, w2h, nullptr, part, nullptr, 128, 32, 32, 8, 4, 64);
            long long n = (long long)BATCH * 128 * 1024;
            hEpiK<<<(unsigned)((n + 255) / 256), 256>>>(
                part, 4, g2_h_b, zr, hprevFp, seq2 + (size_t)t * S2, hspb[t & 1], 128, 1024);
        }
    }

    // ================= Stage 3: 128 -> 128ch, 32x32 -> 16x16 ================
    conv4s2<16, 8, 8><<<dim3(1, 2, TSTEPS * BATCH * 16), dim3(16, 8)>>>(
        seq2, (long long)128 * 1024, (long long)BATCH * 128 * 1024,
        c3_w, c3_b, xsp3, 128, 128, 32, 32);

    float* h3final = nullptr;
    {
        uint4* hspb[2] = { hsp3a, hsp3b };
        float* hfp[2]  = { h3a, h3b };
        for (int t = 0; t < TSTEPS; t++) {
            const uint4* xt = xsp3 + (size_t)t * S3p;
            const uint4* hprevSp = t ? hspb[(t - 1) & 1] : zsp;
            const float* hprevFp = t ? hfp[(t - 1) & 1] : zero0;
            // zr raw split-K=4: Cout=256, ocG=16
            conv5bf<16, 2><<<dim3(1, 2, BATCH * 16 * 4), 128, SM16>>>(
                xt, 128, hprevSp, 128, w3zr, nullptr, part, nullptr, 256, 16, 16, 16, 4, 64);
            {
                long long n = (long long)BATCH * 256 * 256;
                zrEpiK<<<(unsigned)((n + 255) / 256), 256>>>(part, 4, g3_zr_b, hprevFp, zr, rhsp, 256, 256);
            }
            // h raw split-K=8: Cout=128, ocG=8
            conv5bf<16, 2><<<dim3(1, 2, BATCH * 8 * 8), 128, SM16>>>(
                xt, 128, rhsp, 128, w3h, nullptr, part, nullptr, 128, 16, 16, 8, 8, 32);
            long long n = (long long)BATCH * 128 * 256;
            hEpiK<<<(unsigned)((n + 255) / 256), 256>>>(
                part, 8, g3_h_b, zr, hprevFp, hfp[t & 1], hspb[t & 1], 128, 256);
            h3final = hfp[t & 1];
        }
    }

    // ================= Gather outputs =================
    float* out = (float*)d_out;
    int n1 = (int)S1, n2 = (int)S2, n3 = BATCH * 128 * 16 * 16;
    copyk<<<(n1 + 255) / 256, 256>>>(out, seq1 + (size_t)(TSTEPS - 1) * S1, n1);
    copyk<<<(n2 + 255) / 256, 256>>>(out + n1, seq2 + (size_t)(TSTEPS - 1) * S2, n2);
    copyk<<<(n3 + 255) / 256, 256>>>(out + n1 + n2, h3final, n3);
}

// round 11
// speedup vs baseline: 1.4554x; 1.3853x over previous
#include <cuda_runtime.h>
#include <cuda_bf16.h>
#include <math.h>
#include <stdint.h>

#define TSTEPS 12
#define BATCH  8

// ---------------- scratch (static device globals) ---------------------------
__device__ float  g_seq1[(size_t)TSTEPS * BATCH * 64 * 64 * 64];
__device__ float  g_seq2[(size_t)TSTEPS * BATCH * 128 * 32 * 32];
__device__ float  g_h3a [(size_t)BATCH * 128 * 16 * 16];
__device__ float  g_h3b [(size_t)BATCH * 128 * 16 * 16];
// bf16-split activations, PACKED: uint2 per CHANNEL-PAIR per pixel:
//  .x = pack(ch c)   = (lo16(c)<<16)   | hi16(c)      (k-even=hi, k-odd=lo)
//  .y = pack(ch c+4) = (lo16(c+4)<<16) | hi16(c+4)
//  plane index for channel c: (c>>3)*4 + (c&3); slot = (c>>2)&1
__device__ uint2  g_xsp1[(size_t)TSTEPS * BATCH * 32 * 64 * 64];
__device__ uint2  g_xsp2[(size_t)TSTEPS * BATCH * 64 * 32 * 32];
__device__ uint2  g_xsp3[(size_t)TSTEPS * BATCH * 64 * 16 * 16];
__device__ uint2  g_hsp1a[(size_t)BATCH * 32 * 64 * 64];
__device__ uint2  g_hsp1b[(size_t)BATCH * 32 * 64 * 64];
__device__ uint2  g_hsp2a[(size_t)BATCH * 64 * 32 * 32];
__device__ uint2  g_hsp2b[(size_t)BATCH * 64 * 32 * 32];
__device__ uint2  g_hsp3a[(size_t)BATCH * 64 * 16 * 16];
__device__ uint2  g_hsp3b[(size_t)BATCH * 64 * 16 * 16];
__device__ uint2  g_rhsp[(size_t)BATCH * 32 * 64 * 64];
__device__ uint2  g_zsp [(size_t)BATCH * 32 * 64 * 64];
__device__ float  g_zr  [(size_t)BATCH * 128 * 64 * 64];
__device__ float  g_part[(size_t)8388608];
__device__ float  g_zero[(size_t)BATCH * 64 * 64 * 64];
// packed bf16x2 weights (low16 = wHi, high16 = wLo), fp32 weight indexing
__device__ uint32_t g_wcvt[(size_t)5529600];

// ---------------- bf16 split helpers ----------------------------------------
__device__ __forceinline__ uint32_t packSplit(float v) {
    __nv_bfloat16 h = __float2bfloat16(v);
    float hf = __bfloat162float(h);
    __nv_bfloat16 l = __float2bfloat16(v - hf);
    return ((uint32_t)__bfloat16_as_ushort(l) << 16) | (uint32_t)__bfloat16_as_ushort(h);
}
__device__ __forceinline__ float unpackSplit(uint32_t w) {
    return __bfloat162float(__ushort_as_bfloat16((uint16_t)w)) +
           __bfloat162float(__ushort_as_bfloat16((uint16_t)(w >> 16)));
}
__device__ __forceinline__ void storeSplit(uint2* planeBase, int c, long long HW,
                                           long long pix, float v) {
    uint32_t* p = (uint32_t*)(planeBase + (long long)((c >> 3) * 4 + (c & 3)) * HW + pix);
    p[(c >> 2) & 1] = packSplit(v);
}
__device__ __forceinline__ float loadSplit(const uint2* planeBase, int c, long long HW,
                                           long long pix) {
    const uint32_t* p = (const uint32_t*)(planeBase + (long long)((c >> 3) * 4 + (c & 3)) * HW + pix);
    return unpackSplit(p[(c >> 2) & 1]);
}

__global__ void zerok(float* p, uint2* p2, int n, int n2) {
    int i = blockIdx.x * blockDim.x + threadIdx.x;
    if (i < n) p[i] = 0.0f;
    if (i < n2) p2[i] = make_uint2(0, 0);
}
__global__ void copyk(float* __restrict__ dst, const float* __restrict__ src, int n) {
    int i = blockIdx.x * blockDim.x + threadIdx.x;
    if (i < n) dst[i] = src[i];
}
__global__ void wcvtK(const float* __restrict__ w, uint32_t* __restrict__ o, int n) {
    int i = blockIdx.x * blockDim.x + threadIdx.x;
    if (i >= n) return;
    o[i] = packSplit(w[i]);
}

// ---------------- cp.async helpers ------------------------------------------
__device__ __forceinline__ void cp4(uint32_t saddr, const void* g, bool ok) {
    int sz = ok ? 4 : 0;
    asm volatile("cp.async.ca.shared.global [%0], [%1], 4, %2;\n"
                 :: "r"(saddr), "l"(g), "r"(sz));
}
__device__ __forceinline__ void cp8(uint32_t saddr, const void* g, bool ok) {
    int sz = ok ? 8 : 0;
    asm volatile("cp.async.ca.shared.global [%0], [%1], 8, %2;\n"
                 :: "r"(saddr), "l"(g), "r"(sz));
}
__device__ __forceinline__ void cpCommit() {
    asm volatile("cp.async.commit_group;\n" ::: "memory");
}
template <int N>
__device__ __forceinline__ void cpWait() {
    asm volatile("cp.async.wait_group %0;\n" :: "n"(N) : "memory");
}
__device__ __forceinline__ void mma16(float* d, uint32_t a0, uint32_t a1, uint32_t a2,
                                      uint32_t a3, uint32_t b0, uint32_t b1) {
    asm volatile(
        "mma.sync.aligned.m16n8k16.row.col.f32.bf16.bf16.f32 "
        "{%0,%1,%2,%3}, {%4,%5,%6,%7}, {%8,%9}, {%0,%1,%2,%3};"
        : "+f"(d[0]), "+f"(d[1]), "+f"(d[2]), "+f"(d[3])
        : "r"(a0), "r"(a1), "r"(a2), "r"(a3), "r"(b0), "r"(b1));
}

// ---------------------------------------------------------------------------
// Strided conv k4 s2 p1, batched over T. Output written PACKED split (uint2).
// ---------------------------------------------------------------------------
template <int TX, int TY, int OC>
__global__ void conv4s2(const float* __restrict__ in,
                        long long strideB, long long strideT,
                        const float* __restrict__ w, const float* __restrict__ bias,
                        uint2* __restrict__ out,
                        int Cin, int Cout, int Hin, int Win)
{
    const int Hout = Hin >> 1, Wout = Win >> 1;
    const int ocG = Cout / OC;
    int z = blockIdx.z;
    const int ocb = z % ocG; z /= ocG;
    const int b   = z % BATCH;
    const int t   = z / BATCH;
    const int y0  = blockIdx.y * TY;
    const int x0  = blockIdx.x * TX;

    constexpr int IW = 2 * TX + 2;
    constexpr int IH = 2 * TY + 2;
    __shared__ float s_in[IH * IW];
    __shared__ float s_w[OC * 16];

    const int tid = threadIdx.y * TX + threadIdx.x;
    const int nth = TX * TY;
    const float* base = in + (long long)b * strideB + (long long)t * strideT;

    float acc[OC];
#pragma unroll
    for (int oc = 0; oc < OC; oc++) acc[oc] = 0.0f;

    for (int ic = 0; ic < Cin; ic++) {
        const float* src = base + (long long)ic * Hin * Win;
        for (int idx = tid; idx < IH * IW; idx += nth) {
            int iy = 2 * y0 - 1 + idx / IW;
            int ix = 2 * x0 - 1 + idx % IW;
            s_in[idx] = (iy >= 0 && iy < Hin && ix >= 0 && ix < Win)
                            ? src[(long long)iy * Win + ix] : 0.0f;
        }
        for (int idx = tid; idx < OC * 16; idx += nth) {
            int oc = idx / 16, k = idx % 16;
            s_w[idx] = w[(((long long)(ocb * OC + oc)) * Cin + ic) * 16 + k];
        }
        __syncthreads();
#pragma unroll
        for (int kh = 0; kh < 4; kh++)
#pragma unroll
            for (int kw = 0; kw < 4; kw++) {
                float inv = s_in[(2 * threadIdx.y + kh) * IW + 2 * threadIdx.x + kw];
#pragma unroll
                for (int oc = 0; oc < OC; oc++)
                    acc[oc] = fmaf(inv, s_w[oc * 16 + kh * 4 + kw], acc[oc]);
            }
        __syncthreads();
    }

    const int y = y0 + threadIdx.y, x = x0 + threadIdx.x;
    const long long HWo = (long long)Hout * Wout;
    uint2* ob = out + (long long)(t * BATCH + b) * (Cout >> 1) * HWo;
#pragma unroll
    for (int oc = 0; oc < 4; oc++) {
        int c0 = ocb * OC + oc;
        ob[(long long)(ocb * 4 + oc) * HWo + (long long)y * Wout + x]
            = make_uint2(packSplit(acc[oc] + bias[c0]),
                         packSplit(acc[oc + 4] + bias[c0 + 4]));
    }
}

// ---------------------------------------------------------------------------
// 5x5 conv s1 p2, implicit GEMM, split-BF16 mma.sync.m16n8k16, A-side dup.
// Block 128 thr (4 warps). Tile: TX x 8 px rows, 16 output channels.
// B fragment = ONE LDS.64: uint2 (pack(ch c), pack(ch c+4)); k-even=bH, k-odd=bL.
// A: packed weight words dup'd in regs via byte_perm:
//   MMA1 a=dup(wH): wH*bH + wH*bL = wH*b;  MMA2 a=dup(wL): wL*b.  Sum exact.
// smem: input [2buf][4 pair-planes][SPAD] uint2; weights [2buf][25][16oc][4t][2half].
// EPI 0: fused sigmoid -> zr fp32 + rh packed (KS must be 1). EPI 2: raw partial.
// blockIdx.z = ((b*ocG + ocb)*KS + ks)
// ---------------------------------------------------------------------------
template <int TX, int EPI>
__global__ void __launch_bounds__(128)
conv5bf(const uint2* __restrict__ src0, int C0,
        const uint2* __restrict__ src1, int C1,
        const uint32_t* __restrict__ w, const float* __restrict__ bias,
        float* __restrict__ out, uint2* __restrict__ rhOut,
        int Cout, int H, int W, int ocG, int KS, int chunkIC)
{
    constexpr int TY = 8, IW = TX + 4, IH = TY + 4, IN = IH * IW;
    constexpr int SPAD = IN + ((4 - (IN % 16) + 16) % 16);  // SPAD % 16 == 4
    constexpr int PB = TX / 8;
    constexpr int NG = 2 * PB;
    constexpr int WN = 25 * 16 * 4 * 2;                      // 3200 u32 per buf

    extern __shared__ uint32_t smu[];
    uint2*    s_in = (uint2*)smu;          // [2][4][SPAD] uint2
    uint32_t* s_w  = smu + 16 * SPAD;      // [2][WN]

    int z = blockIdx.z;
    const int ks  = z % KS;  z /= KS;
    const int ocb = z % ocG;
    const int b   = z / ocG;
    const int y0  = blockIdx.y * TY;
    const int x0  = blockIdx.x * TX;
    const int tid  = threadIdx.x;
    const int warp = tid >> 5, lane = tid & 31;
    const int gid  = lane >> 2, tig = lane & 3;

    const int Cin = C0 + C1;
    const long long HW = (long long)H * W;
    const int icBeg = ks * chunkIC;
    const int NC = chunkIC / 8;

    const uint32_t sIN = (uint32_t)__cvta_generic_to_shared(s_in);
    const uint32_t sWB = (uint32_t)__cvta_generic_to_shared(s_w);

    auto fillChunk = [&](int buf, int ck) {
        const int cs = icBeg + ck * 8;   // chunks never straddle the C0 boundary
        const uint2* pb = (cs < C0)
            ? src0 + ((long long)b * (C0 >> 1) + (cs >> 1)) * HW
            : src1 + ((long long)b * (C1 >> 1) + ((cs - C0) >> 1)) * HW;
        for (int idx = tid; idx < IN; idx += 128) {
            int rr = idx / IW, cc = idx - rr * IW;
            int iy = y0 - 2 + rr, ix = x0 - 2 + cc;
            bool ok = (iy >= 0) && (iy < H) && (ix >= 0) && (ix < W);
            const uint2* g = ok ? (pb + (long long)iy * W + ix) : pb;
            uint32_t d = sIN + (uint32_t)(buf * 4 * SPAD + idx) * 8u;
#pragma unroll
            for (int t = 0; t < 4; t++)
                cp8(d + (uint32_t)(t * SPAD) * 8u, g + (long long)t * HW, ok);
        }
        for (int idx = tid; idx < WN; idx += 128) {
            // word = ((khkw*16 + oc)*4 + t)*2 + half ; ic = t + 4*half
            int half = idx & 1;
            int t    = (idx >> 1) & 3;
            int oc   = (idx >> 3) & 15;
            int khkw = idx >> 7;
            int ic = t + 4 * half;
            const uint32_t* g = w + ((long long)(ocb * 16 + oc) * Cin + (cs + ic)) * 25 + khkw;
            cp4(sWB + (uint32_t)(buf * WN + idx) * 4u, g, true);
        }
    };

    float acc[NG][4];
#pragma unroll
    for (int g = 0; g < NG; g++)
#pragma unroll
        for (int j = 0; j < 4; j++) acc[g][j] = 0.0f;

    fillChunk(0, 0);
    cpCommit();

    for (int ck = 0; ck < NC; ck++) {
        const int cur = ck & 1;
        if (ck + 1 < NC) fillChunk(cur ^ 1, ck + 1);
        cpCommit();
        cpWait<1>();
        __syncthreads();

        const uint2*    siT = s_in + cur * 4 * SPAD + tig * SPAD;
        const uint32_t* swB = s_w + cur * WN;
        const int prow = 2 * warp;

#pragma unroll
        for (int kh = 0; kh < 5; kh++) {
#pragma unroll
            for (int kw = 0; kw < 5; kw++) {
                const uint32_t* swk = swB + (kh * 5 + kw) * 128;
                uint2 aP0 = *(const uint2*)(swk + (gid * 4 + tig) * 2);        // a0,a2 packed
                uint2 aP1 = *(const uint2*)(swk + ((gid + 8) * 4 + tig) * 2);  // a1,a3 packed
                uint32_t aH0 = __byte_perm(aP0.x, 0, 0x1010), aL0 = __byte_perm(aP0.x, 0, 0x3232);
                uint32_t aH1 = __byte_perm(aP1.x, 0, 0x1010), aL1 = __byte_perm(aP1.x, 0, 0x3232);
                uint32_t aH2 = __byte_perm(aP0.y, 0, 0x1010), aL2 = __byte_perm(aP0.y, 0, 0x3232);
                uint32_t aH3 = __byte_perm(aP1.y, 0, 0x1010), aL3 = __byte_perm(aP1.y, 0, 0x3232);
#pragma unroll
                for (int g = 0; g < NG; g++) {
                    const int r = g / PB, pb2 = g % PB;
                    const int px = (prow + r + kh) * IW + 8 * pb2 + gid + kw;
                    uint2 bb = siT[px];
                    float* d = acc[g];
                    asm volatile(
                        "mma.sync.aligned.m16n8k16.row.col.f32.bf16.bf16.f32 "
                        "{%0,%1,%2,%3}, {%4,%5,%6,%7}, {%8,%9}, {%0,%1,%2,%3};"
                        : "+f"(d[0]), "+f"(d[1]), "+f"(d[2]), "+f"(d[3])
                        : "r"(aH0), "r"(aH1), "r"(aH2), "r"(aH3), "r"(bb.x), "r"(bb.y));
                    asm volatile(
                        "mma.sync.aligned.m16n8k16.row.col.f32.bf16.bf16.f32 "
                        "{%0,%1,%2,%3}, {%4,%5,%6,%7}, {%8,%9}, {%0,%1,%2,%3};"
                        : "+f"(d[0]), "+f"(d[1]), "+f"(d[2]), "+f"(d[3])
                        : "r"(aL0), "r"(aL1), "r"(aL2), "r"(aL3), "r"(bb.x), "r"(bb.y));
                }
            }
        }
        __syncthreads();
    }

    // epilogue: d0:(m=gid, x+0) d1:(gid, x+1) d2:(gid+8, x+0) d3:(gid+8, x+1)
#pragma unroll
    for (int g = 0; g < NG; g++) {
        const int r = g / PB, pb2 = g % PB;
        const int y = y0 + 2 * warp + r;
        const int xb = x0 + 8 * pb2 + 2 * tig;
#pragma unroll
        for (int j = 0; j < 4; j++) {
            const int m = gid + ((j >> 1) << 3);
            const int x = xb + (j & 1);
            const int c = ocb * 16 + m;
            const long long pix = (long long)y * W + x;
            float v = acc[g][j];
            if (EPI == 0) {
                float a = v + bias[c];
                float s = 1.0f / (1.0f + expf(-a));
                out[((long long)b * Cout + c) * HW + pix] = s;
                const int Ch = Cout >> 1;
                if (c >= Ch) {
                    int hc = c - Ch;
                    const uint2* hp = src1 + (long long)b * (C1 >> 1) * HW;
                    float hv = loadSplit(hp, hc, HW, pix);
                    uint2* rp = rhOut + (long long)b * (C1 >> 1) * HW;
                    storeSplit(rp, hc, HW, pix, s * hv);
                }
            } else {
                out[((long long)(ks * BATCH + b) * Cout + c) * HW + pix] = v;
            }
        }
    }
}

// ---------------------------------------------------------------------------
// Split-K epilogues
// ---------------------------------------------------------------------------
__global__ void zrEpiK(const float* __restrict__ part, int KS,
                       const float* __restrict__ bias, const float* __restrict__ hprevFp,
                       float* __restrict__ zrOut, uint2* __restrict__ rhSp,
                       int C2, long long HW)
{
    const long long n = (long long)BATCH * C2 * HW;
    long long i = (long long)blockIdx.x * blockDim.x + threadIdx.x;
    if (i >= n) return;
    float s = 0.0f;
    for (int k = 0; k < KS; k++) s += part[(long long)k * n + i];
    const int c = (int)((i / HW) % C2);
    s += bias[c];
    float sg = 1.0f / (1.0f + expf(-s));
    zrOut[i] = sg;
    const int C = C2 >> 1;
    if (c >= C) {
        long long b = i / (HW * C2);
        long long pix = i % HW;
        int hc = c - C;
        float rv = sg * hprevFp[(b * C + hc) * HW + pix];
        storeSplit(rhSp + b * (C >> 1) * HW, hc, HW, pix, rv);
    }
}

__global__ void hEpiK(const float* __restrict__ part, int KS,
                      const float* __restrict__ bias, const float* __restrict__ zr,
                      const float* __restrict__ hprevFp,
                      float* __restrict__ outFp, uint2* __restrict__ outSp,
                      int C, long long HW)
{
    const long long n = (long long)BATCH * C * HW;
    long long i = (long long)blockIdx.x * blockDim.x + threadIdx.x;
    if (i >= n) return;
    float s = 0.0f;
    for (int k = 0; k < KS; k++) s += part[(long long)k * n + i];
    const int c = (int)((i / HW) % C);
    long long b = i / (HW * C);
    long long pix = i % HW;
    float a = s + bias[c];
    float zv = zr[(b * (2 * C) + c) * HW + pix];
    float hp = hprevFp[i];
    float res = (1.0f - zv) * hp + zv * tanhf(a);
    outFp[i] = res;
    storeSplit(outSp + b * (C >> 1) * HW, c, HW, pix, res);
}

// ---------------------------------------------------------------------------

extern "C" void kernel_launch(void* const* d_in, const int* in_sizes, int n_in,
                              void* d_out, int out_size)
{
    const float* input   = (const float*)d_in[0];
    const float* c1_w    = (const float*)d_in[1];
    const float* c1_b    = (const float*)d_in[2];
    const float* g1_zr_w = (const float*)d_in[3];
    const float* g1_zr_b = (const float*)d_in[4];
    const float* g1_h_w  = (const float*)d_in[5];
    const float* g1_h_b  = (const float*)d_in[6];
    const float* c2_w    = (const float*)d_in[7];
    const float* c2_b    = (const float*)d_in[8];
    const float* g2_zr_w = (const float*)d_in[9];
    const float* g2_zr_b = (const float*)d_in[10];
    const float* g2_h_w  = (const float*)d_in[11];
    const float* g2_h_b  = (const float*)d_in[12];
    const float* c3_w    = (const float*)d_in[13];
    const float* c3_b    = (const float*)d_in[14];
    const float* g3_zr_w = (const float*)d_in[15];
    const float* g3_zr_b = (const float*)d_in[16];
    const float* g3_h_w  = (const float*)d_in[17];
    const float* g3_h_b  = (const float*)d_in[18];

    float *seq1, *seq2, *h3a, *h3b, *zr, *part, *zero0;
    uint2 *xsp1, *xsp2, *xsp3, *hsp1a, *hsp1b, *hsp2a, *hsp2b, *hsp3a, *hsp3b, *rhsp, *zsp;
    uint32_t* wc;
    cudaGetSymbolAddress((void**)&seq1,  g_seq1);
    cudaGetSymbolAddress((void**)&seq2,  g_seq2);
    cudaGetSymbolAddress((void**)&h3a,   g_h3a);
    cudaGetSymbolAddress((void**)&h3b,   g_h3b);
    cudaGetSymbolAddress((void**)&xsp1,  g_xsp1);
    cudaGetSymbolAddress((void**)&xsp2,  g_xsp2);
    cudaGetSymbolAddress((void**)&xsp3,  g_xsp3);
    cudaGetSymbolAddress((void**)&hsp1a, g_hsp1a);
    cudaGetSymbolAddress((void**)&hsp1b, g_hsp1b);
    cudaGetSymbolAddress((void**)&hsp2a, g_hsp2a);
    cudaGetSymbolAddress((void**)&hsp2b, g_hsp2b);
    cudaGetSymbolAddress((void**)&hsp3a, g_hsp3a);
    cudaGetSymbolAddress((void**)&hsp3b, g_hsp3b);
    cudaGetSymbolAddress((void**)&rhsp,  g_rhsp);
    cudaGetSymbolAddress((void**)&zr,    g_zr);
    cudaGetSymbolAddress((void**)&part,  g_part);
    cudaGetSymbolAddress((void**)&zero0, g_zero);
    cudaGetSymbolAddress((void**)&zsp,   g_zsp);
    cudaGetSymbolAddress((void**)&wc,    g_wcvt);

    // converted-weight offsets
    uint32_t* w1zr = wc;                 // 409600
    uint32_t* w1h  = wc + 409600;        // 204800
    uint32_t* w2zr = wc + 614400;        // 1638400
    uint32_t* w2h  = wc + 2252800;       // 819200
    uint32_t* w3zr = wc + 3072000;       // 1638400
    uint32_t* w3h  = wc + 4710400;       // 819200

    // smem sizes (uint2 input planes -> half of R8)
    constexpr int IN32 = 12 * 36, SP32 = IN32 + ((4 - (IN32 % 16) + 16) % 16); // 436
    constexpr int IN16 = 12 * 20, SP16 = IN16 + ((4 - (IN16 % 16) + 16) % 16); // 244
    constexpr int WN2  = 2 * 25 * 16 * 4 * 2;                                   // 6400 u32
    constexpr int SM32 = (16 * SP32 + WN2) * 4;   // 53,504 B
    constexpr int SM16 = (16 * SP16 + WN2) * 4;   // 41,216 B
    cudaFuncSetAttribute(conv5bf<32, 0>, cudaFuncAttributeMaxDynamicSharedMemorySize, SM32);
    cudaFuncSetAttribute(conv5bf<32, 2>, cudaFuncAttributeMaxDynamicSharedMemorySize, SM32);
    cudaFuncSetAttribute(conv5bf<16, 2>, cudaFuncAttributeMaxDynamicSharedMemorySize, SM16);

    // per-launch weight conversion (deterministic, graph-capturable)
    wcvtK<<<(409600 + 255) / 256, 256>>>(g1_zr_w, w1zr, 409600);
    wcvtK<<<(204800 + 255) / 256, 256>>>(g1_h_w,  w1h,  204800);
    wcvtK<<<(1638400 + 255) / 256, 256>>>(g2_zr_w, w2zr, 1638400);
    wcvtK<<<(819200 + 255) / 256, 256>>>(g2_h_w,  w2h,  819200);
    wcvtK<<<(1638400 + 255) / 256, 256>>>(g3_zr_w, w3zr, 1638400);
    wcvtK<<<(819200 + 255) / 256, 256>>>(g3_h_w,  w3h,  819200);

    {   // zero h0 buffers (fp32 + packed split)
        int nz = BATCH * 64 * 64 * 64;
        int nz2 = BATCH * 32 * 64 * 64;
        zerok<<<(nz + 255) / 256, 256>>>(zero0, zsp, nz, nz2);
    }

    const size_t S1  = (size_t)BATCH * 64 * 64 * 64;
    const size_t S2  = (size_t)BATCH * 128 * 32 * 32;
    const size_t S1p = (size_t)BATCH * 32 * 64 * 64;
    const size_t S2p = (size_t)BATCH * 64 * 32 * 32;
    const size_t S3p = (size_t)BATCH * 64 * 16 * 16;

    // ================= Stage 1: 1 -> 64ch, 128x128 -> 64x64 =================
    conv4s2<16, 8, 8><<<dim3(4, 8, TSTEPS * BATCH * 8), dim3(16, 8)>>>(
        input, (long long)TSTEPS * 128 * 128, (long long)128 * 128,
        c1_w, c1_b, xsp1, 1, 64, 128, 128);

    {
        uint2* hspb[2] = { hsp1a, hsp1b };
        for (int t = 0; t < TSTEPS; t++) {
            const uint2* xt = xsp1 + (size_t)t * S1p;
            const uint2* hprevSp = t ? hspb[(t - 1) & 1] : zsp;
            const float* hprevFp = t ? seq1 + (size_t)(t - 1) * S1 : zero0;
            // zr fused (KS=1): Cout=128, ocG=8
            conv5bf<32, 0><<<dim3(2, 8, BATCH * 8), 128, SM32>>>(
                xt, 64, hprevSp, 64, w1zr, g1_zr_b, zr, rhsp, 128, 64, 64, 8, 1, 128);
            // h raw split-K=2: Cout=64, ocG=4
            conv5bf<32, 2><<<dim3(2, 8, BATCH * 4 * 2), 128, SM32>>>(
                xt, 64, rhsp, 64, w1h, nullptr, part, nullptr, 64, 64, 64, 4, 2, 64);
            long long n = (long long)BATCH * 64 * 4096;
            hEpiK<<<(unsigned)((n + 255) / 256), 256>>>(
                part, 2, g1_h_b, zr, hprevFp, seq1 + (size_t)t * S1, hspb[t & 1], 64, 4096);
        }
    }

    // ================= Stage 2: 64 -> 128ch, 64x64 -> 32x32 =================
    conv4s2<16, 8, 8><<<dim3(2, 4, TSTEPS * BATCH * 16), dim3(16, 8)>>>(
        seq1, (long long)64 * 4096, (long long)BATCH * 64 * 4096,
        c2_w, c2_b, xsp2, 64, 128, 64, 64);

    {
        uint2* hspb[2] = { hsp2a, hsp2b };
        for (int t = 0; t < TSTEPS; t++) {
            const uint2* xt = xsp2 + (size_t)t * S2p;
            const uint2* hprevSp = t ? hspb[(t - 1) & 1] : zsp;
            const float* hprevFp = t ? seq2 + (size_t)(t - 1) * S2 : zero0;
            // zr raw split-K=2: Cout=256, ocG=16
            conv5bf<32, 2><<<dim3(1, 4, BATCH * 16 * 2), 128, SM32>>>(
                xt, 128, hprevSp, 128, w2zr, nullptr, part, nullptr, 256, 32, 32, 16, 2, 128);
            {
                long long n = (long long)BATCH * 256 * 1024;
                zrEpiK<<<(unsigned)((n + 255) / 256), 256>>>(part, 2, g2_zr_b, hprevFp, zr, rhsp, 256, 1024);
            }
            // h raw split-K=4: Cout=128, ocG=8
            conv5bf<32, 2><<<dim3(1, 4, BATCH * 8 * 4), 128, SM32>>>(
                xt, 128, rhsp, 128, w2h, nullptr, part, nullptr, 128, 32, 32, 8, 4, 64);
            long long n = (long long)BATCH * 128 * 1024;
            hEpiK<<<(unsigned)((n + 255) / 256), 256>>>(
                part, 4, g2_h_b, zr, hprevFp, seq2 + (size_t)t * S2, hspb[t & 1], 128, 1024);
        }
    }

    // ================= Stage 3: 128 -> 128ch, 32x32 -> 16x16 ================
    conv4s2<16, 8, 8><<<dim3(1, 2, TSTEPS * BATCH * 16), dim3(16, 8)>>>(
        seq2, (long long)128 * 1024, (long long)BATCH * 128 * 1024,
        c3_w, c3_b, xsp3, 128, 128, 32, 32);

    float* h3final = nullptr;
    {
        uint2* hspb[2] = { hsp3a, hsp3b };
        float* hfp[2]  = { h3a, h3b };
        for (int t = 0; t < TSTEPS; t++) {
            const uint2* xt = xsp3 + (size_t)t * S3p;
            const uint2* hprevSp = t ? hspb[(t - 1) & 1] : zsp;
            const float* hprevFp = t ? hfp[(t - 1) & 1] : zero0;
            // zr raw split-K=4: Cout=256, ocG=16
            conv5bf<16, 2><<<dim3(1, 2, BATCH * 16 * 4), 128, SM16>>>(
                xt, 128, hprevSp, 128, w3zr, nullptr, part, nullptr, 256, 16, 16, 16, 4, 64);
            {
                long long n = (long long)BATCH * 256 * 256;
                zrEpiK<<<(unsigned)((n + 255) / 256), 256>>>(part, 4, g3_zr_b, hprevFp, zr, rhsp, 256, 256);
            }
            // h raw split-K=8: Cout=128, ocG=8
            conv5bf<16, 2><<<dim3(1, 2, BATCH * 8 * 8), 128, SM16>>>(
                xt, 128, rhsp, 128, w3h, nullptr, part, nullptr, 128, 16, 16, 8, 8, 32);
            long long n = (long long)BATCH * 128 * 256;
            hEpiK<<<(unsigned)((n + 255) / 256), 256>>>(
                part, 8, g3_h_b, zr, hprevFp, hfp[t & 1], hspb[t & 1], 128, 256);
            h3final = hfp[t & 1];
        }
    }

    // ================= Gather outputs =================
    float* out = (float*)d_out;
    int n1 = (int)S1, n2 = (int)S2, n3 = BATCH * 128 * 16 * 16;
    copyk<<<(n1 + 255) / 256, 256>>>(out, seq1 + (size_t)(TSTEPS - 1) * S1, n1);
    copyk<<<(n2 + 255) / 256, 256>>>(out + n1, seq2 + (size_t)(TSTEPS - 1) * S2, n2);
    copyk<<<(n3 + 255) / 256, 256>>>(out + n1 + n2, h3final, n3);
}